// round 16
// baseline (speedup 1.0000x reference)
#include <cuda_runtime.h>

#define D 128
#define H 128
#define LN_EPS 1e-3f

// ---------------- scratch (device globals; no allocation) ----------------
__device__ float    g_dAT[128 * 1024];    // A^T : [h][pos_row]
__device__ float    g_dBT[128 * 512];     // B^T : [h][col_row]
__device__ float4   g_rStat[1024];        // {sum, sumsq, dot_g, 0}
__device__ float4   g_cStat[512];
__device__ float    g_rowSum[1024];
__device__ float    g_segSum[64 * 512];   // [n_seq][n_col]
__device__ int      g_segId[1024];
__device__ float    g_G, g_C0;
__device__ unsigned g_cnt;                // zero-init; self-resetting
__device__ unsigned g_flag;
__device__ unsigned g_sense[1024];

__device__ __forceinline__ void grid_barrier(int nblk) {
    __syncthreads();
    if (threadIdx.x == 0) {
        unsigned s = g_sense[blockIdx.x] ^ 1u;
        g_sense[blockIdx.x] = s;
        __threadfence();
        unsigned old = atomicAdd(&g_cnt, 1u);
        if (old == (unsigned)(nblk - 1)) {
            g_cnt = 0u;
            __threadfence();
            *(volatile unsigned*)&g_flag = s;
        } else {
            while (*(volatile unsigned*)&g_flag != s) { }
        }
        __threadfence();
    }
    __syncthreads();
}

__device__ __forceinline__ float f4sel(const float4& v, int kk) {
    return (kk == 0) ? v.x : (kk == 1) ? v.y : (kk == 2) ? v.z : v.w;
}

__global__ void __launch_bounds__(256, 2)
k_fused(const float* __restrict__ seqf, const float* __restrict__ colf,
        const float* __restrict__ Ws, const float* __restrict__ bs,
        const float* __restrict__ Wc, const float* __restrict__ bc,
        const float* __restrict__ Wm, const float* __restrict__ bm,
        const float* __restrict__ gamma, const float* __restrict__ beta,
        const float* __restrict__ Wo, const float* __restrict__ bo,
        const int* __restrict__ lens,
        float* __restrict__ E,
        int n_pos, int n_col, int n_seq, int nblk) {
    const int tid = threadIdx.x;
    const int bid = blockIdx.x;

    // pool: prep  = sW[64][128](8192) + fbufP(512) + fbufC(256) + vbufP(512) + vbufC(256) = 9728 floats
    //       gemm  = As[64][68](4352) + Bs[64][36](2304) = 6656 floats
    __shared__ float pool[9728];
    __shared__ float colAcc[64];
    __shared__ float sstat[2][3][3][4];     // [sub][rowslot][stat][warp-in-sub]
    __shared__ int   soff[65];

    float* sW    = pool;                    // [64][128]
    float* fbufP = pool + 8192;             // [4][128]
    float* fbufC = fbufP + 512;             // [2][128]
    float* vbufP = fbufC + 256;             // [4][128]
    float* vbufC = vbufP + 512;             // [2][128]

    // ---- zero accumulators (one element per thread grid-wide) ----
    {
        int gt = bid * 256 + tid;
        int total = n_pos + n_seq * n_col;
        for (int i = gt; i < total; i += nblk * 256) {
            if (i < n_pos) g_rowSum[i] = 0.f;
            else           g_segSum[i - n_pos] = 0.f;
        }
    }

    // ===================== phase A : prep (4 pos rows + 2 col rows per block) ==========
    const int sub = tid >> 7;               // 0,1
    const int h   = tid & 127;
    const int w4  = (tid >> 5) & 3;         // warp within sub
    const int p0g = bid * 4;                // first pos row of this block
    const int c0g = bid * 2;                // first col row

    // load features: pos rows (512 floats = 128 f4), col rows (256 floats = 64 f4)
    if (tid < 128) {
        ((float4*)fbufP)[tid] = ((const float4*)(seqf + (size_t)p0g * D))[tid];
    } else if (tid < 192) {
        ((float4*)fbufC)[tid - 128] = ((const float4*)(colf + (size_t)c0g * D))[tid - 128];
    }
    __syncthreads();

    float accP0, accP1, accC;

    // ---- layer 1, pos rows (Ws) ----
    accP0 = bs[h]; accP1 = accP0;
    #pragma unroll
    for (int c = 0; c < 2; c++) {
        #pragma unroll
        for (int j = 0; j < 8; j++) {
            int i = tid + j * 256;
            int k = i >> 5, c4 = i & 31;
            *(float4*)&sW[k * 128 + c4 * 4] = *(const float4*)&Ws[(c * 64 + k) * H + c4 * 4];
        }
        __syncthreads();
        #pragma unroll 4
        for (int k4 = 0; k4 < 16; k4++) {
            float4 a0 = *(const float4*)&fbufP[(sub * 2 + 0) * 128 + c * 64 + k4 * 4];
            float4 a1 = *(const float4*)&fbufP[(sub * 2 + 1) * 128 + c * 64 + k4 * 4];
            #pragma unroll
            for (int kk = 0; kk < 4; kk++) {
                float w = sW[(k4 * 4 + kk) * 128 + h];
                accP0 = fmaf(f4sel(a0, kk), w, accP0);
                accP1 = fmaf(f4sel(a1, kk), w, accP1);
            }
        }
        __syncthreads();
    }
    vbufP[(sub * 2 + 0) * 128 + h] = fmaxf(accP0, 0.f);
    vbufP[(sub * 2 + 1) * 128 + h] = fmaxf(accP1, 0.f);

    // ---- layer 1, col rows (Wc) ----
    accC = bc[h];
    #pragma unroll
    for (int c = 0; c < 2; c++) {
        __syncthreads();
        #pragma unroll
        for (int j = 0; j < 8; j++) {
            int i = tid + j * 256;
            int k = i >> 5, c4 = i & 31;
            *(float4*)&sW[k * 128 + c4 * 4] = *(const float4*)&Wc[(c * 64 + k) * H + c4 * 4];
        }
        __syncthreads();
        #pragma unroll 4
        for (int k4 = 0; k4 < 16; k4++) {
            float4 a0 = *(const float4*)&fbufC[sub * 128 + c * 64 + k4 * 4];
            #pragma unroll
            for (int kk = 0; kk < 4; kk++) {
                float w = sW[(k4 * 4 + kk) * 128 + h];
                accC = fmaf(f4sel(a0, kk), w, accC);
            }
        }
    }
    __syncthreads();
    vbufC[sub * 128 + h] = fmaxf(accC, 0.f);

    // ---- layer 2 (Wm) for all 6 rows ----
    accP0 = 0.f; accP1 = 0.f; accC = bm[h];
    #pragma unroll
    for (int c = 0; c < 2; c++) {
        __syncthreads();
        #pragma unroll
        for (int j = 0; j < 8; j++) {
            int i = tid + j * 256;
            int k = i >> 5, c4 = i & 31;
            *(float4*)&sW[k * 128 + c4 * 4] = *(const float4*)&Wm[(c * 64 + k) * H + c4 * 4];
        }
        __syncthreads();
        #pragma unroll 4
        for (int k4 = 0; k4 < 16; k4++) {
            float4 a0 = *(const float4*)&vbufP[(sub * 2 + 0) * 128 + c * 64 + k4 * 4];
            float4 a1 = *(const float4*)&vbufP[(sub * 2 + 1) * 128 + c * 64 + k4 * 4];
            float4 ac = *(const float4*)&vbufC[sub * 128 + c * 64 + k4 * 4];
            #pragma unroll
            for (int kk = 0; kk < 4; kk++) {
                float w = sW[(k4 * 4 + kk) * 128 + h];
                accP0 = fmaf(f4sel(a0, kk), w, accP0);
                accP1 = fmaf(f4sel(a1, kk), w, accP1);
                accC  = fmaf(f4sel(ac, kk), w, accC);
            }
        }
    }

    // ---- transposed stores + per-row stats ----
    const float gh = gamma[h] * Wo[h];
    {
        float us[3] = {accP0, accP1, accC};
        #pragma unroll
        for (int r = 0; r < 3; r++) {
            float u = us[r];
            if (r < 2) g_dAT[(size_t)h * n_pos + p0g + sub * 2 + r] = u;
            else       g_dBT[(size_t)h * n_col + c0g + sub] = u;
            float a = u, b2 = u * u, cg = u * gh;
            #pragma unroll
            for (int o = 16; o > 0; o >>= 1) {
                a  += __shfl_down_sync(0xFFFFFFFFu, a,  o);
                b2 += __shfl_down_sync(0xFFFFFFFFu, b2, o);
                cg += __shfl_down_sync(0xFFFFFFFFu, cg, o);
            }
            if ((h & 31) == 0) {
                sstat[sub][r][0][w4] = a;
                sstat[sub][r][1][w4] = b2;
                sstat[sub][r][2][w4] = cg;
            }
        }
    }
    __syncthreads();
    if (h < 3) {
        int r = h;
        float4 st;
        st.x = sstat[sub][r][0][0] + sstat[sub][r][0][1] + sstat[sub][r][0][2] + sstat[sub][r][0][3];
        st.y = sstat[sub][r][1][0] + sstat[sub][r][1][1] + sstat[sub][r][1][2] + sstat[sub][r][1][3];
        st.z = sstat[sub][r][2][0] + sstat[sub][r][2][1] + sstat[sub][r][2][2] + sstat[sub][r][2][3];
        st.w = 0.f;
        if (r < 2) g_rStat[p0g + sub * 2 + r] = st;
        else       g_cStat[c0g + sub] = st;
    }

    // ---- block 0: scalars + segment ids ----
    if (bid == 0) {
        if (tid < 128) {
            float a = gamma[tid] * Wo[tid];
            float b = beta[tid] * Wo[tid];
            #pragma unroll
            for (int o = 16; o > 0; o >>= 1) {
                a += __shfl_down_sync(0xFFFFFFFFu, a, o);
                b += __shfl_down_sync(0xFFFFFFFFu, b, o);
            }
            if ((tid & 31) == 0) { colAcc[tid >> 5] = a; colAcc[4 + (tid >> 5)] = b; }
        }
        __syncthreads();
        if (tid == 0) {
            g_G  = colAcc[0] + colAcc[1] + colAcc[2] + colAcc[3];
            g_C0 = colAcc[4] + colAcc[5] + colAcc[6] + colAcc[7] + bo[0];
            int a2 = 0;
            for (int s = 0; s < n_seq; s++) { soff[s] = a2; a2 += lens[s]; }
            soff[n_seq] = a2;
        }
        __syncthreads();
        for (int p = tid; p < n_pos; p += 256) {
            int s = 0;
            while (s + 1 < n_seq && p >= soff[s + 1]) s++;
            g_segId[p] = s;
        }
    }

    grid_barrier(nblk);

    // ===================== phase B : GEMM (64x32 tile) =====================
    const int nTN = n_col >> 5;                 // 16
    const int bx = bid & (nTN - 1), by = bid / nTN;
    const int m0 = by * 64, n0 = bx * 32;
    const int tx = tid & 7, ty = tid >> 3;      // tx 0..7 (n), ty 0..31 (m)

    float (*As)[68] = (float(*)[68])pool;
    float (*Bs)[36] = (float(*)[36])(pool + 64 * 68);

    float acc[2][4];
    #pragma unroll
    for (int i = 0; i < 2; i++)
        #pragma unroll
        for (int j = 0; j < 4; j++) acc[i][j] = 0.f;

    // prefetch chunk 0
    float4 pa[4], pb[2];
    #pragma unroll
    for (int i = 0; i < 4; i++) {
        int idx = tid + i * 256;
        int k = idx >> 4, m4 = idx & 15;
        pa[i] = *(const float4*)&g_dAT[(size_t)k * n_pos + m0 + m4 * 4];
    }
    #pragma unroll
    for (int i = 0; i < 2; i++) {
        int idx = tid + i * 256;
        int k = idx >> 3, n4 = idx & 7;
        pb[i] = *(const float4*)&g_dBT[(size_t)k * n_col + n0 + n4 * 4];
    }

    #pragma unroll
    for (int kc = 0; kc < H; kc += 64) {
        #pragma unroll
        for (int i = 0; i < 4; i++) {
            int idx = tid + i * 256;
            int k = idx >> 4, m4 = idx & 15;
            *(float4*)&As[k][m4 * 4] = pa[i];
        }
        #pragma unroll
        for (int i = 0; i < 2; i++) {
            int idx = tid + i * 256;
            int k = idx >> 3, n4 = idx & 7;
            *(float4*)&Bs[k][n4 * 4] = pb[i];
        }
        __syncthreads();
        if (kc + 64 < H) {
            #pragma unroll
            for (int i = 0; i < 4; i++) {
                int idx = tid + i * 256;
                int k = idx >> 4, m4 = idx & 15;
                pa[i] = *(const float4*)&g_dAT[(size_t)(kc + 64 + k) * n_pos + m0 + m4 * 4];
            }
            #pragma unroll
            for (int i = 0; i < 2; i++) {
                int idx = tid + i * 256;
                int k = idx >> 3, n4 = idx & 7;
                pb[i] = *(const float4*)&g_dBT[(size_t)(kc + 64 + k) * n_col + n0 + n4 * 4];
            }
        }
        #pragma unroll 8
        for (int k = 0; k < 64; k++) {
            float2 a = *(const float2*)&As[k][ty * 2];
            float4 b = *(const float4*)&Bs[k][tx * 4];
            acc[0][0] = fmaf(a.x, b.x, acc[0][0]); acc[0][1] = fmaf(a.x, b.y, acc[0][1]);
            acc[0][2] = fmaf(a.x, b.z, acc[0][2]); acc[0][3] = fmaf(a.x, b.w, acc[0][3]);
            acc[1][0] = fmaf(a.y, b.x, acc[1][0]); acc[1][1] = fmaf(a.y, b.y, acc[1][1]);
            acc[1][2] = fmaf(a.y, b.z, acc[1][2]); acc[1][3] = fmaf(a.y, b.w, acc[1][3]);
        }
        __syncthreads();
    }

    // ---- epilogue: LN closed form + exp + fused sums ----
    const float G = g_G, C0 = g_C0;
    const int mrow0 = m0 + ty * 2;
    float4 rs[2];
    rs[0] = g_rStat[mrow0];
    rs[1] = g_rStat[mrow0 + 1];
    float4 cs[4];
    #pragma unroll
    for (int j = 0; j < 4; j++) cs[j] = g_cStat[n0 + tx * 4 + j];

    float rowpart[2] = {0.f, 0.f};
    float colpart[4] = {0.f, 0.f, 0.f, 0.f};

    #pragma unroll
    for (int i = 0; i < 2; i++) {
        #pragma unroll
        for (int j = 0; j < 4; j++) {
            float dot = acc[i][j];
            float mu = (rs[i].x + cs[j].x) * (1.0f / H);
            float var = (rs[i].y + 2.f * dot + cs[j].y) * (1.0f / H) - mu * mu;
            float inv = rsqrtf(var + LN_EPS);
            float raw = fmaf(rs[i].z + cs[j].z - mu * G, inv, C0);
            float e = __expf(raw);
            acc[i][j] = e;
            rowpart[i] += e;
            colpart[j] += e;
        }
    }

    // row sums: reduce across 8 tx lanes
    #pragma unroll
    for (int i = 0; i < 2; i++) {
        float v = rowpart[i];
        #pragma unroll
        for (int o = 4; o > 0; o >>= 1) v += __shfl_down_sync(0xFFFFFFFFu, v, o, 8);
        if (tx == 0) atomicAdd(&g_rowSum[mrow0 + i], v);
    }

    // column sums: reduce the 4 ty-groups within each warp, then across warps via smem
    #pragma unroll
    for (int j = 0; j < 4; j++) {
        colpart[j] += __shfl_down_sync(0xFFFFFFFFu, colpart[j], 16);
        colpart[j] += __shfl_down_sync(0xFFFFFFFFu, colpart[j], 8);
    }

    const int s0 = g_segId[mrow0], s1 = g_segId[mrow0 + 1];
    const int sA = g_segId[m0], sB = g_segId[m0 + 63];
    if (sA == sB) {
        if (tid < 32) colAcc[tid] = 0.f;
        __syncthreads();
        if ((tid & 31) < 8) {
            #pragma unroll
            for (int j = 0; j < 4; j++) atomicAdd(&colAcc[tx * 4 + j], colpart[j]);
        }
        __syncthreads();
        if (tid < 32) atomicAdd(&g_segSum[sA * n_col + n0 + tid], colAcc[tid]);
    } else {
        #pragma unroll
        for (int i = 0; i < 2; i++) {
            int s = i ? s1 : s0;
            #pragma unroll
            for (int j = 0; j < 4; j++)
                atomicAdd(&g_segSum[s * n_col + n0 + tx * 4 + j], acc[i][j]);
        }
    }

    grid_barrier(nblk);

    // ---- finalize: Mc + Ms - Mc*Ms, single store ----
    #pragma unroll
    for (int i = 0; i < 2; i++) {
        int m = mrow0 + i;
        float Rinv = __frcp_rn(g_rowSum[m]);
        int s = i ? s1 : s0;
        const float4 ss = *(const float4*)&g_segSum[s * n_col + n0 + tx * 4];
        float mcx = acc[i][0] * Rinv, msx = acc[i][0] * __frcp_rn(ss.x);
        float mcy = acc[i][1] * Rinv, msy = acc[i][1] * __frcp_rn(ss.y);
        float mcz = acc[i][2] * Rinv, msz = acc[i][2] * __frcp_rn(ss.z);
        float mcw = acc[i][3] * Rinv, msw = acc[i][3] * __frcp_rn(ss.w);
        float4 o;
        o.x = mcx + msx - mcx * msx;
        o.y = mcy + msy - mcy * msy;
        o.z = mcz + msz - mcz * msz;
        o.w = mcw + msw - mcw * msw;
        *(float4*)&E[(size_t)m * n_col + n0 + tx * 4] = o;
    }
}

// ---------------- host launcher ----------------
extern "C" void kernel_launch(void* const* d_in, const int* in_sizes, int n_in,
                              void* d_out, int out_size) {
    const float* seqf  = (const float*)d_in[0];
    const float* colf  = (const float*)d_in[1];
    const int*   lens  = (const int*)  d_in[2];
    const float* Ws    = (const float*)d_in[3];
    const float* bs    = (const float*)d_in[4];
    const float* Wc    = (const float*)d_in[5];
    const float* bc    = (const float*)d_in[6];
    const float* Wm    = (const float*)d_in[7];
    const float* bm    = (const float*)d_in[8];
    const float* gamma = (const float*)d_in[9];
    const float* beta  = (const float*)d_in[10];
    const float* Wo    = (const float*)d_in[11];
    const float* bo    = (const float*)d_in[12];

    int n_seq = in_sizes[2];
    int n_pos = in_sizes[0] / D;   // 1024
    int n_col = in_sizes[1] / D;   // 512
    float* E = (float*)d_out;

    int nblk = (n_pos / 64) * (n_col / 32);   // 256 blocks, 2/SM
    k_fused<<<nblk, 256>>>(seqf, colf, Ws, bs, Wc, bc, Wm, bm,
                           gamma, beta, Wo, bo, lens, E,
                           n_pos, n_col, n_seq, nblk);
}

// round 17
// speedup vs baseline: 1.6776x; 1.6776x over previous
#include <cuda_runtime.h>

#define D 128
#define H 128
#define LN_EPS 1e-3f

// ---------------- scratch (device globals; no allocation) ----------------
__device__ float    g_dAT[128 * 1024];    // A^T : [h][pos_row]
__device__ float    g_dBT[128 * 512];     // B^T : [h][col_row]
__device__ float4   g_rStat[1024];        // {sum, sumsq, dot_g, 0} per position row
__device__ float4   g_cStat[512];
__device__ float    g_rowSum[1024];
__device__ float    g_segSum[64 * 512];   // [n_seq, n_col]
__device__ int      g_segId[1024];
__device__ float    g_G, g_C0;
__device__ unsigned g_cnt;                // zero-init; self-resetting
__device__ unsigned g_flag;
__device__ unsigned g_sense[512];

__device__ __forceinline__ void grid_barrier(int nblk) {
    __syncthreads();
    if (threadIdx.x == 0) {
        unsigned s = g_sense[blockIdx.x] ^ 1u;
        g_sense[blockIdx.x] = s;
        __threadfence();
        unsigned old = atomicAdd(&g_cnt, 1u);
        if (old == (unsigned)(nblk - 1)) {
            g_cnt = 0u;
            __threadfence();
            *(volatile unsigned*)&g_flag = s;
        } else {
            while (*(volatile unsigned*)&g_flag != s) { }
        }
        __threadfence();
    }
    __syncthreads();
}

__device__ __forceinline__ float f4sel(const float4& v, int kk) {
    return (kk == 0) ? v.x : (kk == 1) ? v.y : (kk == 2) ? v.z : v.w;
}

// fused two-layer precompute for R rows; float4 activation reads, pipelined W LDG
template <int R>
__device__ __forceinline__ void do_prep(
    const float* __restrict__ feat, const float* __restrict__ W1,
    const float* __restrict__ b1, const float* __restrict__ Wm, float bmh,
    float gh, float* __restrict__ dT, int stride, int r0,
    float4* __restrict__ statOut, float* fbuf, float* vbuf,
    float (*sstat)[4][3][4], int sub, int h) {

    #pragma unroll
    for (int r = 0; r < R; r++) fbuf[r * 128 + h] = feat[r * D + h];
    __syncthreads();

    float acc[R];
    float bb = b1[h];
    #pragma unroll
    for (int r = 0; r < R; r++) acc[r] = bb;
    {
        float w[4], wn[4];
        #pragma unroll
        for (int kk = 0; kk < 4; kk++) w[kk] = W1[kk * H + h];
        #pragma unroll 8
        for (int k4 = 0; k4 < 32; k4++) {
            if (k4 < 31) {
                #pragma unroll
                for (int kk = 0; kk < 4; kk++) wn[kk] = W1[((k4 + 1) * 4 + kk) * H + h];
            }
            float4 f4[R];
            #pragma unroll
            for (int r = 0; r < R; r++) f4[r] = *(const float4*)&fbuf[r * 128 + k4 * 4];
            #pragma unroll
            for (int kk = 0; kk < 4; kk++) {
                #pragma unroll
                for (int r = 0; r < R; r++) acc[r] = fmaf(f4sel(f4[r], kk), w[kk], acc[r]);
            }
            #pragma unroll
            for (int kk = 0; kk < 4; kk++) w[kk] = wn[kk];
        }
    }
    #pragma unroll
    for (int r = 0; r < R; r++) vbuf[r * 128 + h] = fmaxf(acc[r], 0.f);
    __syncthreads();

    #pragma unroll
    for (int r = 0; r < R; r++) acc[r] = bmh;
    {
        float w[4], wn[4];
        #pragma unroll
        for (int kk = 0; kk < 4; kk++) w[kk] = Wm[kk * H + h];
        #pragma unroll 8
        for (int k4 = 0; k4 < 32; k4++) {
            if (k4 < 31) {
                #pragma unroll
                for (int kk = 0; kk < 4; kk++) wn[kk] = Wm[((k4 + 1) * 4 + kk) * H + h];
            }
            float4 f4[R];
            #pragma unroll
            for (int r = 0; r < R; r++) f4[r] = *(const float4*)&vbuf[r * 128 + k4 * 4];
            #pragma unroll
            for (int kk = 0; kk < 4; kk++) {
                #pragma unroll
                for (int r = 0; r < R; r++) acc[r] = fmaf(f4sel(f4[r], kk), w[kk], acc[r]);
            }
            #pragma unroll
            for (int kk = 0; kk < 4; kk++) w[kk] = wn[kk];
        }
    }

    #pragma unroll
    for (int r = 0; r < R; r++) {
        float u = acc[r];
        dT[(size_t)h * stride + r0 + r] = u;    // transposed store
        float a = u, b2 = u * u, c = u * gh;
        #pragma unroll
        for (int o = 16; o > 0; o >>= 1) {
            a  += __shfl_down_sync(0xFFFFFFFFu, a,  o);
            b2 += __shfl_down_sync(0xFFFFFFFFu, b2, o);
            c  += __shfl_down_sync(0xFFFFFFFFu, c,  o);
        }
        if ((h & 31) == 0) {
            sstat[sub][r][0][h >> 5] = a;
            sstat[sub][r][1][h >> 5] = b2;
            sstat[sub][r][2][h >> 5] = c;
        }
    }
    __syncthreads();
    if (h < R) {
        int r = h;
        float4 st;
        st.x = sstat[sub][r][0][0] + sstat[sub][r][0][1] + sstat[sub][r][0][2] + sstat[sub][r][0][3];
        st.y = sstat[sub][r][1][0] + sstat[sub][r][1][1] + sstat[sub][r][1][2] + sstat[sub][r][1][3];
        st.z = sstat[sub][r][2][0] + sstat[sub][r][2][1] + sstat[sub][r][2][2] + sstat[sub][r][2][3];
        st.w = 0.f;
        statOut[r0 + r] = st;
    }
}

__global__ void __launch_bounds__(256, 2)
k_fused(const float* __restrict__ seqf, const float* __restrict__ colf,
        const float* __restrict__ Ws, const float* __restrict__ bs,
        const float* __restrict__ Wc, const float* __restrict__ bc,
        const float* __restrict__ Wm, const float* __restrict__ bm,
        const float* __restrict__ gamma, const float* __restrict__ beta,
        const float* __restrict__ Wo, const float* __restrict__ bo,
        const int* __restrict__ lens,
        float* __restrict__ E,
        int n_pos, int n_col, int n_seq, int nblk) {
    const int tid = threadIdx.x;
    const int bid = blockIdx.x;

    __shared__ float pool[64 * 68 + 64 * 36];   // GEMM: As[64][68] | Bs[64][36]; prep reuses
    __shared__ float colAcc[32];
    __shared__ float sstat[2][4][3][4];
    __shared__ int   soff[65];

    // ---- zero accumulators (spread grid-wide) ----
    {
        int gt = bid * 256 + tid;
        int total = n_pos + n_seq * n_col;
        for (int i = gt; i < total; i += nblk * 256) {
            if (i < n_pos) g_rowSum[i] = 0.f;
            else           g_segSum[i - n_pos] = 0.f;
        }
    }

    // ===================== phase A : prep =====================
    const int nPosB = n_pos >> 3;               // 128 blocks x 8 pos rows
    const int sub = tid >> 7;                   // 0,1
    const int h   = tid & 127;
    const float gh = gamma[h] * Wo[h];

    if (bid < nPosB) {
        const int r0 = bid * 8 + sub * 4;
        do_prep<4>(seqf + (size_t)r0 * D, Ws, bs, Wm, 0.f, gh,
                   g_dAT, n_pos, r0, g_rStat,
                   pool + sub * 512, pool + 1024 + sub * 512,
                   sstat, sub, h);
    } else {
        const int r0 = (bid - nPosB) * 4 + sub * 2;
        do_prep<2>(colf + (size_t)r0 * D, Wc, bc, Wm, bm[h], gh,
                   g_dBT, n_col, r0, g_cStat,
                   pool + sub * 256, pool + 512 + sub * 256,
                   sstat, sub, h);
    }

    // ---- last (light) block: scalars + segment ids ----
    if (bid == nblk - 1) {
        if (tid < 128) {
            float a = gamma[tid] * Wo[tid];
            float b = beta[tid] * Wo[tid];
            #pragma unroll
            for (int o = 16; o > 0; o >>= 1) {
                a += __shfl_down_sync(0xFFFFFFFFu, a, o);
                b += __shfl_down_sync(0xFFFFFFFFu, b, o);
            }
            if ((tid & 31) == 0) { colAcc[tid >> 5] = a; colAcc[4 + (tid >> 5)] = b; }
        }
        __syncthreads();
        if (tid == 0) {
            g_G  = colAcc[0] + colAcc[1] + colAcc[2] + colAcc[3];
            g_C0 = colAcc[4] + colAcc[5] + colAcc[6] + colAcc[7] + bo[0];
            int a2 = 0;
            for (int s = 0; s < n_seq; s++) { soff[s] = a2; a2 += lens[s]; }
            soff[n_seq] = a2;
        }
        __syncthreads();
        for (int p = tid; p < n_pos; p += 256) {
            int s = 0;
            while (s + 1 < n_seq && p >= soff[s + 1]) s++;
            g_segId[p] = s;
        }
    }

    grid_barrier(nblk);

    // ===================== phase B : GEMM (64x32 tile) =====================
    const int nTN = n_col >> 5;                 // 16
    const int bx = bid % nTN, by = bid / nTN;
    const int m0 = by * 64, n0 = bx * 32;
    const int tx = tid & 7, ty = tid >> 3;      // tx 0..7 (n), ty 0..31 (m)

    float (*As)[68] = (float(*)[68])pool;
    float (*Bs)[36] = (float(*)[36])(pool + 64 * 68);

    float acc[2][4];
    #pragma unroll
    for (int i = 0; i < 2; i++)
        #pragma unroll
        for (int j = 0; j < 4; j++) acc[i][j] = 0.f;

    // prefetch chunk 0
    float4 pa[4], pb[2];
    #pragma unroll
    for (int i = 0; i < 4; i++) {
        int idx = tid + i * 256;
        int k = idx >> 4, m4 = idx & 15;
        pa[i] = *(const float4*)&g_dAT[(size_t)k * n_pos + m0 + m4 * 4];
    }
    #pragma unroll
    for (int i = 0; i < 2; i++) {
        int idx = tid + i * 256;
        int k = idx >> 3, n4 = idx & 7;
        pb[i] = *(const float4*)&g_dBT[(size_t)k * n_col + n0 + n4 * 4];
    }

    #pragma unroll
    for (int kc = 0; kc < H; kc += 64) {
        #pragma unroll
        for (int i = 0; i < 4; i++) {
            int idx = tid + i * 256;
            int k = idx >> 4, m4 = idx & 15;
            *(float4*)&As[k][m4 * 4] = pa[i];
        }
        #pragma unroll
        for (int i = 0; i < 2; i++) {
            int idx = tid + i * 256;
            int k = idx >> 3, n4 = idx & 7;
            *(float4*)&Bs[k][n4 * 4] = pb[i];
        }
        __syncthreads();
        if (kc + 64 < H) {
            #pragma unroll
            for (int i = 0; i < 4; i++) {
                int idx = tid + i * 256;
                int k = idx >> 4, m4 = idx & 15;
                pa[i] = *(const float4*)&g_dAT[(size_t)(kc + 64 + k) * n_pos + m0 + m4 * 4];
            }
            #pragma unroll
            for (int i = 0; i < 2; i++) {
                int idx = tid + i * 256;
                int k = idx >> 3, n4 = idx & 7;
                pb[i] = *(const float4*)&g_dBT[(size_t)(kc + 64 + k) * n_col + n0 + n4 * 4];
            }
        }
        #pragma unroll 16
        for (int k = 0; k < 64; k++) {
            float2 a = *(const float2*)&As[k][ty * 2];
            float4 b = *(const float4*)&Bs[k][tx * 4];
            acc[0][0] = fmaf(a.x, b.x, acc[0][0]); acc[0][1] = fmaf(a.x, b.y, acc[0][1]);
            acc[0][2] = fmaf(a.x, b.z, acc[0][2]); acc[0][3] = fmaf(a.x, b.w, acc[0][3]);
            acc[1][0] = fmaf(a.y, b.x, acc[1][0]); acc[1][1] = fmaf(a.y, b.y, acc[1][1]);
            acc[1][2] = fmaf(a.y, b.z, acc[1][2]); acc[1][3] = fmaf(a.y, b.w, acc[1][3]);
        }
        __syncthreads();
    }

    // ---- epilogue: LN closed form + exp + fused sums ----
    const float G = g_G, C0 = g_C0;
    const int mrow0 = m0 + ty * 2;
    float4 rs[2];
    rs[0] = g_rStat[mrow0];
    rs[1] = g_rStat[mrow0 + 1];
    float4 cs[4];
    #pragma unroll
    for (int j = 0; j < 4; j++) cs[j] = g_cStat[n0 + tx * 4 + j];

    float rowpart[2] = {0.f, 0.f};
    float colpart[4] = {0.f, 0.f, 0.f, 0.f};

    #pragma unroll
    for (int i = 0; i < 2; i++) {
        #pragma unroll
        for (int j = 0; j < 4; j++) {
            float dot = acc[i][j];
            float mu = (rs[i].x + cs[j].x) * (1.0f / H);
            float var = (rs[i].y + 2.f * dot + cs[j].y) * (1.0f / H) - mu * mu;
            float inv = rsqrtf(var + LN_EPS);
            float raw = fmaf(rs[i].z + cs[j].z - mu * G, inv, C0);
            float e = __expf(raw);
            acc[i][j] = e;
            rowpart[i] += e;
            colpart[j] += e;
        }
    }

    // row sums: reduce across 8 tx lanes
    #pragma unroll
    for (int i = 0; i < 2; i++) {
        float v = rowpart[i];
        #pragma unroll
        for (int o = 4; o > 0; o >>= 1) v += __shfl_down_sync(0xFFFFFFFFu, v, o, 8);
        if (tx == 0) atomicAdd(&g_rowSum[mrow0 + i], v);
    }

    // column sums: reduce the 4 ty-groups within each warp, then across warps via smem
    #pragma unroll
    for (int j = 0; j < 4; j++) {
        colpart[j] += __shfl_down_sync(0xFFFFFFFFu, colpart[j], 16);
        colpart[j] += __shfl_down_sync(0xFFFFFFFFu, colpart[j], 8);
    }

    const int s0 = g_segId[mrow0], s1 = g_segId[mrow0 + 1];
    const int sA = g_segId[m0], sB = g_segId[m0 + 63];
    if (sA == sB) {
        if (tid < 32) colAcc[tid] = 0.f;
        __syncthreads();
        if ((tid & 31) < 8) {
            #pragma unroll
            for (int j = 0; j < 4; j++) atomicAdd(&colAcc[tx * 4 + j], colpart[j]);
        }
        __syncthreads();
        if (tid < 32) atomicAdd(&g_segSum[sA * n_col + n0 + tid], colAcc[tid]);
    } else {
        #pragma unroll
        for (int i = 0; i < 2; i++) {
            int s = i ? s1 : s0;
            #pragma unroll
            for (int j = 0; j < 4; j++)
                atomicAdd(&g_segSum[s * n_col + n0 + tx * 4 + j], acc[i][j]);
        }
    }

    grid_barrier(nblk);

    // ---- finalize: Mc + Ms - Mc*Ms, single store ----
    #pragma unroll
    for (int i = 0; i < 2; i++) {
        int m = mrow0 + i;
        float Rinv = __frcp_rn(g_rowSum[m]);
        int s = i ? s1 : s0;
        const float4 ss = *(const float4*)&g_segSum[s * n_col + n0 + tx * 4];
        float mcx = acc[i][0] * Rinv, msx = acc[i][0] * __frcp_rn(ss.x);
        float mcy = acc[i][1] * Rinv, msy = acc[i][1] * __frcp_rn(ss.y);
        float mcz = acc[i][2] * Rinv, msz = acc[i][2] * __frcp_rn(ss.z);
        float mcw = acc[i][3] * Rinv, msw = acc[i][3] * __frcp_rn(ss.w);
        float4 o;
        o.x = mcx + msx - mcx * msx;
        o.y = mcy + msy - mcy * msy;
        o.z = mcz + msz - mcz * msz;
        o.w = mcw + msw - mcw * msw;
        *(float4*)&E[(size_t)m * n_col + n0 + tx * 4] = o;
    }
}

// ---------------- host launcher ----------------
extern "C" void kernel_launch(void* const* d_in, const int* in_sizes, int n_in,
                              void* d_out, int out_size) {
    const float* seqf  = (const float*)d_in[0];
    const float* colf  = (const float*)d_in[1];
    const int*   lens  = (const int*)  d_in[2];
    const float* Ws    = (const float*)d_in[3];
    const float* bs    = (const float*)d_in[4];
    const float* Wc    = (const float*)d_in[5];
    const float* bc    = (const float*)d_in[6];
    const float* Wm    = (const float*)d_in[7];
    const float* bm    = (const float*)d_in[8];
    const float* gamma = (const float*)d_in[9];
    const float* beta  = (const float*)d_in[10];
    const float* Wo    = (const float*)d_in[11];
    const float* bo    = (const float*)d_in[12];

    int n_seq = in_sizes[2];
    int n_pos = in_sizes[0] / D;   // 1024
    int n_col = in_sizes[1] / D;   // 512
    float* E = (float*)d_out;

    int nblk = (n_pos / 64) * (n_col / 32);   // 256 blocks, 2/SM
    k_fused<<<nblk, 256>>>(seqf, colf, Ws, bs, Wc, bc, Wm, bm,
                           gamma, beta, Wo, bo, lens, E,
                           n_pos, n_col, n_seq, nblk);
}